// round 15
// baseline (speedup 1.0000x reference)
#include <cuda_runtime.h>
#include <cuda_bf16.h>

#define BS 2
#define NQ 8192
#define NV 6890
#define NF 13776
#define EPSF 1e-7f
#define R2F 0.01f        // f32(0.1*0.1) — matches JAX constant folding
#define NEG_R (-0.1f)
#define THRESHF 0.001f

#define GRIDC 10
#define NSUB (GRIDC * GRIDC * GRIDC)
#define CAP 512          // per-cell neighborhood list capacity (λ≈186)
#define CAPSH 9
#define IMAXI 0x7fffffff
#define QBLOCKS (BS * NQ / 8)    // 1 query/warp, 8 warps/block -> 2048 blocks

// Zero-initialized at module load; the last query block re-zeros counters
// and accumulators at the end of each replay (graph-replay consistent).
__device__ float4 g_vn[BS * NV];              // (nx,ny,nz,count)
__device__ int    g_cnt[BS * NSUB];           // neighborhood-list counters
__device__ float4 g_nb[BS * NSUB * CAP];      // packed neighborhood lists
__device__ float  g_loss[2];                  // sum, count
__device__ unsigned int g_done;

// ---------------------------------------------------------------------------
// K1: build. (a) each (vertex, offset) pair inserts the vertex into the
// neighborhood list of one of its 27 neighbor cells; (b) face-normal scatter.
// ---------------------------------------------------------------------------
__global__ void build_kernel(const float* __restrict__ h_state,
                             const int* __restrict__ h_faces) {
    int t = blockIdx.x * blockDim.x + threadIdx.x;

    if (t < 27 * BS * NV) {
        int rep = t / (BS * NV);           // neighbor offset 0..26
        int u   = t - rep * (BS * NV);
        int b = u / NV, v = u - b * NV;

        const float* xs = h_state + b * 6 * NV;
        float x = __ldg(xs + v), y = __ldg(xs + NV + v), z = __ldg(xs + 2 * NV + v);
        int ix = min(max((int)(x * 10.0f), 0), GRIDC - 1);
        int iy = min(max((int)(y * 10.0f), 0), GRIDC - 1);
        int iz = min(max((int)(z * 10.0f), 0), GRIDC - 1);

        int dz = rep / 9;
        int r2 = rep - dz * 9;
        int dy = r2 / 3;
        int dx = r2 - dy * 3;
        int cx = ix + dx - 1, cy = iy + dy - 1, cz = iz + dz - 1;
        if (cx >= 0 && cx < GRIDC && cy >= 0 && cy < GRIDC && cz >= 0 && cz < GRIDC) {
            int c = ((b * GRIDC + cy) * GRIDC + cx) * GRIDC + cz;
            int slot = atomicAdd(&g_cnt[c], 1);
            if (slot < CAP)
                g_nb[((size_t)c << CAPSH) + slot] = make_float4(x, y, z, __int_as_float(v));
        }
    }

    if (t < BS * NF) {
        int b = t / NF, f = t - b * NF;
        const int* F = h_faces + b * 3 * NF;
        int i0 = __ldg(F + f), i1 = __ldg(F + NF + f), i2 = __ldg(F + 2 * NF + f);

        const float* xs = h_state + b * 6 * NV;
        const float* ys = xs + NV;
        const float* zs = xs + 2 * NV;

        float x0 = __ldg(xs + i0), y0 = __ldg(ys + i0), z0 = __ldg(zs + i0);
        float e1x = __ldg(xs + i1) - x0, e1y = __ldg(ys + i1) - y0, e1z = __ldg(zs + i1) - z0;
        float e2x = __ldg(xs + i2) - x0, e2y = __ldg(ys + i2) - y0, e2z = __ldg(zs + i2) - z0;

        float nx = e1y * e2z - e1z * e2y;
        float ny = e1z * e2x - e1x * e2z;
        float nz = e1x * e2y - e1y * e2x;
        float nrm = sqrtf(nx * nx + ny * ny + nz * nz) + EPSF;
        nx /= nrm; ny /= nrm; nz /= nrm;

        int base = b * NV;
        float one = 1.0f;
        asm volatile("red.global.add.v4.f32 [%0], {%1, %2, %3, %4};"
                     :: "l"(&g_vn[base + i0]), "f"(nx), "f"(ny), "f"(nz), "f"(one) : "memory");
        asm volatile("red.global.add.v4.f32 [%0], {%1, %2, %3, %4};"
                     :: "l"(&g_vn[base + i1]), "f"(nx), "f"(ny), "f"(nz), "f"(one) : "memory");
        asm volatile("red.global.add.v4.f32 [%0], {%1, %2, %3, %4};"
                     :: "l"(&g_vn[base + i2]), "f"(nx), "f"(ny), "f"(nz), "f"(one) : "memory");
    }
}

// ---------------------------------------------------------------------------
// K2: fused query + finalize. ONE query per warp; a single uniform 32-lane
// loop over the precomputed neighborhood list (no column decode, no
// divergence). Full-warp REDUX min-4 merge; loss tail on lanes 0-3; last
// block finalizes + re-zeros.
// ---------------------------------------------------------------------------
__global__ void __launch_bounds__(256)
query_kernel(const float* __restrict__ pred,
             const float* __restrict__ h_state,
             float* __restrict__ out) {
    __shared__ float s_sum[8];
    __shared__ float s_cnt[8];
    __shared__ bool  s_last;

    int gq   = (blockIdx.x * blockDim.x + threadIdx.x) >> 5;   // query id
    int lane = threadIdx.x & 31;
    int wib  = threadIdx.x >> 5;

    int b = gq >> 13;                  // batch (NQ = 8192)

    const float* P = pred + (size_t)gq * 3;
    float px = __ldg(P), py = __ldg(P + 1), pz = __ldg(P + 2);

    int ix = min(max((int)(px * 10.0f), 0), GRIDC - 1);
    int iy = min(max((int)(py * 10.0f), 0), GRIDC - 1);
    int iz = min(max((int)(pz * 10.0f), 0), GRIDC - 1);
    int c = ((b * GRIDC + iy) * GRIDC + ix) * GRIDC + iz;

    int n = min(__ldg(&g_cnt[c]), CAP);
    const float4* B = g_nb + ((size_t)c << CAPSH);

    int b0 = IMAXI, b1 = IMAXI, b2 = IMAXI, b3 = IMAXI;

    for (int s = lane; s < n; s += 32) {
        float4 v = __ldg(B + s);
        float ddx = px - v.x, ddy = py - v.y, ddz = pz - v.z;
        if (ddx * ddx + ddy * ddy + ddz * ddz < R2F) {
            int id = __float_as_int(v.w);
            if (id < b3) {
                b3 = id;
                if (b3 < b2) { int tt = b2; b2 = b3; b3 = tt; }
                if (b2 < b1) { int tt = b1; b1 = b2; b2 = tt; }
                if (b1 < b0) { int tt = b0; b0 = b1; b1 = tt; }
            }
        }
    }

    // Full-warp merge: 4 successive minima via REDUX; lane k keeps k-th.
    int mine = IMAXI, first = 0, cnt = 0;
    #pragma unroll
    for (int k = 0; k < 4; k++) {
        int m = (int)__reduce_min_sync(0xffffffffu, (unsigned)b0);
        if (lane == k) mine = m;
        if (k == 0 && m != IMAXI) first = m;
        if (m != IMAXI) cnt++;
        if (m != IMAXI && b0 == m) { b0 = b1; b1 = b2; b2 = b3; b3 = IMAXI; }
    }

    // Loss tail: lanes 0-3 handle one neighbor each.
    float contrib = 0.0f, nmv = 0.0f;
    if (lane < 4) {
        int i = (lane < cnt) ? mine : first;   // idx=0 when no hits (argmax)
        const float* xs = h_state + b * 6 * NV;
        float vx = __ldg(xs + i);
        float vy = __ldg(xs + NV + i);
        float vz = __ldg(xs + 2 * NV + i);
        float4 vn = __ldg(&g_vn[b * NV + i]);
        float denom = vn.w + EPSF;
        float gx = vn.x / denom, gy = vn.y / denom, gz = vn.z / denom;
        float nr = sqrtf(gx * gx + gy * gy + gz * gz) + EPSF;
        gx /= nr; gy /= nr; gz /= nr;
        float dot = (px - vx) * gx + (py - vy) * gy + (pz - vz) * gz;
        float valid = (dot >= NEG_R) ? (dot - THRESHF) : 0.0f;
        if (valid < 0.0f) { contrib = valid; nmv = 1.0f; }
    }
    contrib += __shfl_xor_sync(0xffffffffu, contrib, 1);
    contrib += __shfl_xor_sync(0xffffffffu, contrib, 2);
    nmv     += __shfl_xor_sync(0xffffffffu, nmv, 1);
    nmv     += __shfl_xor_sync(0xffffffffu, nmv, 2);

    if (lane == 0) {
        float pp = contrib / (nmv + EPSF);
        float pp2 = pp * pp;
        s_sum[wib] = pp2;
        s_cnt[wib] = (pp2 > 0.0f) ? 1.0f : 0.0f;
    }
    __syncthreads();

    if (threadIdx.x == 0) {
        float bs_ = 0.0f, bc_ = 0.0f;
        #pragma unroll
        for (int i = 0; i < 8; i++) { bs_ += s_sum[i]; bc_ += s_cnt[i]; }
        atomicAdd(&g_loss[0], bs_);
        atomicAdd(&g_loss[1], bc_);
        __threadfence();
        unsigned int nd = atomicAdd(&g_done, 1u);
        s_last = (nd == (unsigned int)(gridDim.x - 1));
    }
    __syncthreads();

    // Last block: finalize + re-zero scratch for the next graph replay.
    if (s_last) {
        int t = threadIdx.x;
        if (t == 0) {
            float ls = atomicAdd(&g_loss[0], 0.0f);
            float lc = atomicAdd(&g_loss[1], 0.0f);
            out[0] = ls / (lc + EPSF);     // LOSS_WEIGHT = 1
            g_loss[0] = 0.0f;
            g_loss[1] = 0.0f;
            g_done = 0u;
        }
        float4 z4 = make_float4(0.0f, 0.0f, 0.0f, 0.0f);
        for (int i = t; i < BS * NV; i += 256) g_vn[i] = z4;
        for (int i = t; i < BS * NSUB; i += 256) g_cnt[i] = 0;
    }
}

// ---------------------------------------------------------------------------
extern "C" void kernel_launch(void* const* d_in, const int* in_sizes, int n_in,
                              void* d_out, int out_size) {
    const float* pred    = (const float*)d_in[0];   // (2, 8192, 3)
    const float* h_state = (const float*)d_in[2];   // (2, 6, 6890)
    const int*   h_faces = (const int*)d_in[3];     // (2, 3, 13776)
    float* out = (float*)d_out;

    int bn = 27 * BS * NV;   // covers BS*NF too (372060 > 27552)
    build_kernel<<<(bn + 127) / 128, 128>>>(h_state, h_faces);

    query_kernel<<<QBLOCKS, 256>>>(pred, h_state, out);
}

// round 16
// speedup vs baseline: 1.2796x; 1.2796x over previous
#include <cuda_runtime.h>
#include <cuda_bf16.h>

#define BS 2
#define NQ 8192
#define NV 6890
#define NF 13776
#define EPSF 1e-7f
#define R2F 0.01f        // f32(0.1*0.1) — matches JAX constant folding
#define R2PRUNE 0.010001f // conservative box-prune threshold
#define NEG_R (-0.1f)
#define THRESHF 0.001f

#define GRIDC 10
#define NSUB (GRIDC * GRIDC * GRIDC)
#define CAP3 32          // own-cell bin capacity (λ=6.9)
#define CAP 256          // pruned neighborhood list capacity (λ≈142)
#define CAPSH 8
#define IMAXI 0x7fffffff
#define QBLOCKS (BS * NQ / 8)    // 1 query/warp, 8 warps/block -> 2048 blocks

// Zero-initialized at module load; the last query block re-zeros everything
// at the end of each replay so the captured graph is self-consistent.
__device__ float4 g_vn[BS * NV];              // (nx,ny,nz,count)
__device__ int    g_cnt3[BS * NSUB];          // own-cell bin counters
__device__ float4 g_bins3[BS * NSUB * CAP3];  // own-cell bins
__device__ int    g_cnt[BS * NSUB];           // neighborhood-list counts
__device__ float4 g_nb[BS * NSUB * CAP];      // pruned neighborhood lists
__device__ float  g_loss[2];                  // sum, count
__device__ unsigned int g_done;

// ---------------------------------------------------------------------------
// K1: own-cell vertex binning (low-contention atomics) + face-normal scatter
// ---------------------------------------------------------------------------
__global__ void build_kernel(const float* __restrict__ h_state,
                             const int* __restrict__ h_faces) {
    int t = blockIdx.x * blockDim.x + threadIdx.x;

    if (t < BS * NV) {
        int b = t / NV, v = t - b * NV;
        const float* xs = h_state + b * 6 * NV;
        float x = __ldg(xs + v), y = __ldg(xs + NV + v), z = __ldg(xs + 2 * NV + v);
        int ix = min(max((int)(x * 10.0f), 0), GRIDC - 1);
        int iy = min(max((int)(y * 10.0f), 0), GRIDC - 1);
        int iz = min(max((int)(z * 10.0f), 0), GRIDC - 1);
        int sc = ((b * GRIDC + iy) * GRIDC + ix) * GRIDC + iz;
        int slot = atomicAdd(&g_cnt3[sc], 1);
        if (slot < CAP3)
            g_bins3[((size_t)sc << 5) + slot] = make_float4(x, y, z, __int_as_float(v));
    }

    if (t < BS * NF) {
        int b = t / NF, f = t - b * NF;
        const int* F = h_faces + b * 3 * NF;
        int i0 = __ldg(F + f), i1 = __ldg(F + NF + f), i2 = __ldg(F + 2 * NF + f);

        const float* xs = h_state + b * 6 * NV;
        const float* ys = xs + NV;
        const float* zs = xs + 2 * NV;

        float x0 = __ldg(xs + i0), y0 = __ldg(ys + i0), z0 = __ldg(zs + i0);
        float e1x = __ldg(xs + i1) - x0, e1y = __ldg(ys + i1) - y0, e1z = __ldg(zs + i1) - z0;
        float e2x = __ldg(xs + i2) - x0, e2y = __ldg(ys + i2) - y0, e2z = __ldg(zs + i2) - z0;

        float nx = e1y * e2z - e1z * e2y;
        float ny = e1z * e2x - e1x * e2z;
        float nz = e1x * e2y - e1y * e2x;
        float nrm = sqrtf(nx * nx + ny * ny + nz * nz) + EPSF;
        nx /= nrm; ny /= nrm; nz /= nrm;

        int base = b * NV;
        float one = 1.0f;
        asm volatile("red.global.add.v4.f32 [%0], {%1, %2, %3, %4};"
                     :: "l"(&g_vn[base + i0]), "f"(nx), "f"(ny), "f"(nz), "f"(one) : "memory");
        asm volatile("red.global.add.v4.f32 [%0], {%1, %2, %3, %4};"
                     :: "l"(&g_vn[base + i1]), "f"(nx), "f"(ny), "f"(nz), "f"(one) : "memory");
        asm volatile("red.global.add.v4.f32 [%0], {%1, %2, %3, %4};"
                     :: "l"(&g_vn[base + i2]), "f"(nx), "f"(ny), "f"(nz), "f"(one) : "memory");
    }
}

// ---------------------------------------------------------------------------
// K2: expand — one block per cell gathers 27 neighbor bins into a packed,
// box-pruned list. Zero global atomics (smem counter only).
// ---------------------------------------------------------------------------
__global__ void __launch_bounds__(128)
expand_kernel() {
    __shared__ int s_n[27];      // neighbor bin counts (0 if OOB)
    __shared__ int s_sc[27];     // neighbor bin cell ids
    __shared__ int s_cnt;        // output slot counter

    int c = blockIdx.x;          // cell id: ((b*G + iy)*G + ix)*G + iz
    int tid = threadIdx.x;

    int c2 = c;
    int iz = c2 % GRIDC; c2 /= GRIDC;
    int ix = c2 % GRIDC; c2 /= GRIDC;
    int iy = c2 % GRIDC;
    int b  = c2 / GRIDC;

    // Query-cell box bounds
    float xlo = ix * 0.1f, xhi = (ix + 1) * 0.1f;
    float ylo = iy * 0.1f, yhi = (iy + 1) * 0.1f;
    float zlo = iz * 0.1f, zhi = (iz + 1) * 0.1f;

    if (tid == 0) s_cnt = 0;
    if (tid < 27) {
        int dz = tid / 9;
        int r2 = tid - dz * 9;
        int dy = r2 / 3;
        int dx = r2 - dy * 3;
        int cx = ix + dx - 1, cy = iy + dy - 1, cz = iz + dz - 1;
        bool ok = (cx >= 0) && (cx < GRIDC) && (cy >= 0) && (cy < GRIDC)
               && (cz >= 0) && (cz < GRIDC);
        int nc = ((b * GRIDC + cy) * GRIDC + cx) * GRIDC + cz;
        s_sc[tid] = nc;
        s_n[tid]  = ok ? min(g_cnt3[nc], CAP3) : 0;
    }
    __syncthreads();

    float4* OUT = g_nb + ((size_t)c << CAPSH);

    // Flattened loop over 27 * CAP3 virtual slots
    for (int s = tid; s < 27 * CAP3; s += 128) {
        int k = s >> 5;            // neighbor index
        int idx = s & 31;          // slot within bin
        if (idx < s_n[k]) {
            float4 v = g_bins3[((size_t)s_sc[k] << 5) + idx];
            float ddx = fmaxf(fmaxf(xlo - v.x, v.x - xhi), 0.0f);
            float ddy = fmaxf(fmaxf(ylo - v.y, v.y - yhi), 0.0f);
            float ddz = fmaxf(fmaxf(zlo - v.z, v.z - zhi), 0.0f);
            if (ddx * ddx + ddy * ddy + ddz * ddz < R2PRUNE) {
                int slot = atomicAdd(&s_cnt, 1);
                if (slot < CAP) OUT[slot] = v;
            }
        }
    }
    __syncthreads();
    if (tid == 0) g_cnt[c] = min(s_cnt, CAP);
}

// ---------------------------------------------------------------------------
// K3: fused query + finalize. ONE query per warp; uniform 32-lane loop over
// the pruned neighborhood list, unrolled x2 (two loads in flight). Full-warp
// REDUX min-4 merge; loss tail on lanes 0-3; last block finalizes + re-zeros.
// ---------------------------------------------------------------------------
__global__ void __launch_bounds__(256)
query_kernel(const float* __restrict__ pred,
             const float* __restrict__ h_state,
             float* __restrict__ out) {
    __shared__ float s_sum[8];
    __shared__ float s_cnt_[8];
    __shared__ bool  s_last;

    int gq   = (blockIdx.x * blockDim.x + threadIdx.x) >> 5;   // query id
    int lane = threadIdx.x & 31;
    int wib  = threadIdx.x >> 5;

    int b = gq >> 13;                  // batch (NQ = 8192)

    const float* P = pred + (size_t)gq * 3;
    float px = __ldg(P), py = __ldg(P + 1), pz = __ldg(P + 2);

    int ix = min(max((int)(px * 10.0f), 0), GRIDC - 1);
    int iy = min(max((int)(py * 10.0f), 0), GRIDC - 1);
    int iz = min(max((int)(pz * 10.0f), 0), GRIDC - 1);
    int c = ((b * GRIDC + iy) * GRIDC + ix) * GRIDC + iz;

    int n = __ldg(&g_cnt[c]);
    const float4* B = g_nb + ((size_t)c << CAPSH);

    int b0 = IMAXI, b1 = IMAXI, b2 = IMAXI, b3 = IMAXI;

    for (int s = lane; s < n; s += 64) {
        float4 v1 = __ldg(B + s);
        int s2 = s + 32;
        bool p2 = s2 < n;
        float4 v2;
        if (p2) v2 = __ldg(B + s2);

        float ddx = px - v1.x, ddy = py - v1.y, ddz = pz - v1.z;
        if (ddx * ddx + ddy * ddy + ddz * ddz < R2F) {
            int id = __float_as_int(v1.w);
            if (id < b3) {
                b3 = id;
                if (b3 < b2) { int tt = b2; b2 = b3; b3 = tt; }
                if (b2 < b1) { int tt = b1; b1 = b2; b2 = tt; }
                if (b1 < b0) { int tt = b0; b0 = b1; b1 = tt; }
            }
        }
        if (p2) {
            float ex = px - v2.x, ey = py - v2.y, ez = pz - v2.z;
            if (ex * ex + ey * ey + ez * ez < R2F) {
                int id = __float_as_int(v2.w);
                if (id < b3) {
                    b3 = id;
                    if (b3 < b2) { int tt = b2; b2 = b3; b3 = tt; }
                    if (b2 < b1) { int tt = b1; b1 = b2; b2 = tt; }
                    if (b1 < b0) { int tt = b0; b0 = b1; b1 = tt; }
                }
            }
        }
    }

    // Full-warp merge: 4 successive minima via REDUX; lane k keeps k-th.
    int mine = IMAXI, first = 0, cnt = 0;
    #pragma unroll
    for (int k = 0; k < 4; k++) {
        int m = (int)__reduce_min_sync(0xffffffffu, (unsigned)b0);
        if (lane == k) mine = m;
        if (k == 0 && m != IMAXI) first = m;
        if (m != IMAXI) cnt++;
        if (m != IMAXI && b0 == m) { b0 = b1; b1 = b2; b2 = b3; b3 = IMAXI; }
    }

    // Loss tail: lanes 0-3 handle one neighbor each.
    float contrib = 0.0f, nmv = 0.0f;
    if (lane < 4) {
        int i = (lane < cnt) ? mine : first;   // idx=0 when no hits (argmax)
        const float* xs = h_state + b * 6 * NV;
        float vx = __ldg(xs + i);
        float vy = __ldg(xs + NV + i);
        float vz = __ldg(xs + 2 * NV + i);
        float4 vn = __ldg(&g_vn[b * NV + i]);
        float denom = vn.w + EPSF;
        float gx = vn.x / denom, gy = vn.y / denom, gz = vn.z / denom;
        float nr = sqrtf(gx * gx + gy * gy + gz * gz) + EPSF;
        gx /= nr; gy /= nr; gz /= nr;
        float dot = (px - vx) * gx + (py - vy) * gy + (pz - vz) * gz;
        float valid = (dot >= NEG_R) ? (dot - THRESHF) : 0.0f;
        if (valid < 0.0f) { contrib = valid; nmv = 1.0f; }
    }
    contrib += __shfl_xor_sync(0xffffffffu, contrib, 1);
    contrib += __shfl_xor_sync(0xffffffffu, contrib, 2);
    nmv     += __shfl_xor_sync(0xffffffffu, nmv, 1);
    nmv     += __shfl_xor_sync(0xffffffffu, nmv, 2);

    if (lane == 0) {
        float pp = contrib / (nmv + EPSF);
        float pp2 = pp * pp;
        s_sum[wib] = pp2;
        s_cnt_[wib] = (pp2 > 0.0f) ? 1.0f : 0.0f;
    }
    __syncthreads();

    if (threadIdx.x == 0) {
        float bs_ = 0.0f, bc_ = 0.0f;
        #pragma unroll
        for (int i = 0; i < 8; i++) { bs_ += s_sum[i]; bc_ += s_cnt_[i]; }
        atomicAdd(&g_loss[0], bs_);
        atomicAdd(&g_loss[1], bc_);
        __threadfence();
        unsigned int nd = atomicAdd(&g_done, 1u);
        s_last = (nd == (unsigned int)(gridDim.x - 1));
    }
    __syncthreads();

    // Last block: finalize + re-zero scratch for the next graph replay.
    if (s_last) {
        int t = threadIdx.x;
        if (t == 0) {
            float ls = atomicAdd(&g_loss[0], 0.0f);
            float lc = atomicAdd(&g_loss[1], 0.0f);
            out[0] = ls / (lc + EPSF);     // LOSS_WEIGHT = 1
            g_loss[0] = 0.0f;
            g_loss[1] = 0.0f;
            g_done = 0u;
        }
        float4 z4 = make_float4(0.0f, 0.0f, 0.0f, 0.0f);
        for (int i = t; i < BS * NV; i += 256) g_vn[i] = z4;
        for (int i = t; i < BS * NSUB; i += 256) { g_cnt3[i] = 0; g_cnt[i] = 0; }
    }
}

// ---------------------------------------------------------------------------
extern "C" void kernel_launch(void* const* d_in, const int* in_sizes, int n_in,
                              void* d_out, int out_size) {
    const float* pred    = (const float*)d_in[0];   // (2, 8192, 3)
    const float* h_state = (const float*)d_in[2];   // (2, 6, 6890)
    const int*   h_faces = (const int*)d_in[3];     // (2, 3, 13776)
    float* out = (float*)d_out;

    int bn = BS * NF;   // covers BS*NV too
    build_kernel<<<(bn + 127) / 128, 128>>>(h_state, h_faces);

    expand_kernel<<<BS * NSUB, 128>>>();

    query_kernel<<<QBLOCKS, 256>>>(pred, h_state, out);
}